// round 10
// baseline (speedup 1.0000x reference)
#include <cuda_runtime.h>
#include <math.h>

#define NN 50000          // N_NODES == M_NODES
#define KNBR 32
#define F 128
#define WSIZE 3
#define RPB 32            // rows per block (4 warps x 8 rows)

typedef unsigned long long ull;

// Scratch (device globals: allocation-free per harness rules)
__device__ float g_h[(size_t)NN * F];     // h = input @ W  (fp32)
__device__ float g_hc1[NN];               // fl32( fp64-accurate h . c1 )
__device__ float g_hc2[NN];               // fl32( fp64-accurate h . c2 )

// ---- packed f32x2 helpers ----
static __device__ __forceinline__ ull pack2(float lo, float hi) {
    ull r;
    asm("mov.b64 %0, {%1, %2};" : "=l"(r) : "f"(lo), "f"(hi));
    return r;
}
static __device__ __forceinline__ void unpack2(ull v, float& lo, float& hi) {
    asm("mov.b64 {%0, %1}, %2;" : "=f"(lo), "=f"(hi) : "l"(v));
}
static __device__ __forceinline__ void ffma2(ull& d, ull a, ull b) {
    asm("fma.rn.f32x2 %0, %1, %2, %0;" : "+l"(d) : "l"(a), "l"(b));
}

// ============================================================================
// Kernel A: h = input @ W — PURE GEMM (fp64 epilogue split out).
// ARITHMETIC CONTRACT (bitwise, frozen): for each (row, col),
//   acc.lo = sum over even k ascending of in[k]*W[k][c]
//   acc.hi = sum over odd  k ascending;  h = acc.lo + acc.hi
// block = 128 threads (4 warps), 32 rows/block, 8 rows/warp, 4 cols/lane.
// ============================================================================
__global__ void __launch_bounds__(128) gemm_kernel(
    const float* __restrict__ inp,
    const float* __restrict__ W)
{
    __shared__ float s_in[RPB][F];   // 16 KB

    const int tid  = threadIdx.x;
    const int lane = tid & 31;
    const int warp = tid >> 5;
    const int row0 = blockIdx.x * RPB;

    // stage 32 input rows (1024 float4; 8 per thread)
    #pragma unroll
    for (int i = 0; i < 8; i++) {
        const int idx   = tid + i * 128;
        const int row   = idx >> 5;
        const int chunk = idx & 31;
        int grow = row0 + row;
        if (grow >= NN) grow = NN - 1;         // clamp (tail block)
        ((float4*)&s_in[row][0])[chunk] =
            ((const float4*)(inp + (size_t)grow * F))[chunk];
    }
    __syncthreads();

    ull acc[8][4];
    #pragma unroll
    for (int r = 0; r < 8; r++)
        #pragma unroll
        for (int i = 0; i < 4; i++)
            acc[r][i] = 0ULL;

    const int colbase = lane * 4;
    const int rbase   = warp * 8;

    #pragma unroll 4
    for (int k = 0; k < F; k += 2) {
        const float4 wa = *(const float4*)(W + (size_t)k * F + colbase);
        const float4 wb = *(const float4*)(W + (size_t)(k + 1) * F + colbase);
        const ull wp0 = pack2(wa.x, wb.x);
        const ull wp1 = pack2(wa.y, wb.y);
        const ull wp2 = pack2(wa.z, wb.z);
        const ull wp3 = pack2(wa.w, wb.w);
        #pragma unroll
        for (int r = 0; r < 8; r++) {
            const ull ip = *(const ull*)&s_in[rbase + r][k];  // == pack2(s[k],s[k+1])
            ffma2(acc[r][0], ip, wp0);
            ffma2(acc[r][1], ip, wp1);
            ffma2(acc[r][2], ip, wp2);
            ffma2(acc[r][3], ip, wp3);
        }
    }

    #pragma unroll
    for (int r = 0; r < 8; r++) {
        const int row = row0 + rbase + r;
        if (row >= NN) continue;
        float4 hv;
        float lo, hi;
        unpack2(acc[r][0], lo, hi); hv.x = lo + hi;
        unpack2(acc[r][1], lo, hi); hv.y = lo + hi;
        unpack2(acc[r][2], lo, hi); hv.z = lo + hi;
        unpack2(acc[r][3], lo, hi); hv.w = lo + hi;
        *(float4*)(g_h + (size_t)row * F + colbase) = hv;
    }
}

// ============================================================================
// Kernel A2: hc1/hc2 dot products, fp64, bitwise-identical to the old fused
// epilogue: lane owns cols lane*4..lane*4+3, per-lane partial =
// x*c.x + y*c.y + z*c.z + w*c.w in that order (fp64), then shfl_down tree.
// One warp per 8 rows (grid covers all rows).
// ============================================================================
__global__ void __launch_bounds__(256) hc_kernel(
    const float* __restrict__ c1,
    const float* __restrict__ c2)
{
    const int warp = threadIdx.x >> 5;
    const int lane = threadIdx.x & 31;
    const int colbase = lane * 4;
    const int rowbase = (blockIdx.x * 8 + warp) * 8;   // 8 rows per warp

    const float4 cv1 = *(const float4*)(c1 + colbase);
    const float4 cv2 = *(const float4*)(c2 + colbase);

    #pragma unroll
    for (int r = 0; r < 8; r++) {
        const int row = rowbase + r;
        if (row >= NN) break;
        const float4 hv = *(const float4*)(g_h + (size_t)row * F + colbase);

        double d1 = (double)hv.x * (double)cv1.x + (double)hv.y * (double)cv1.y
                  + (double)hv.z * (double)cv1.z + (double)hv.w * (double)cv1.w;
        double d2 = (double)hv.x * (double)cv2.x + (double)hv.y * (double)cv2.y
                  + (double)hv.z * (double)cv2.z + (double)hv.w * (double)cv2.w;
        #pragma unroll
        for (int off = 16; off > 0; off >>= 1) {
            d1 += __shfl_down_sync(0xffffffffu, d1, off);
            d2 += __shfl_down_sync(0xffffffffu, d2, off);
        }
        if (lane == 0) {
            g_hc1[row] = (float)d1;
            g_hc2[row] = (float)d2;
        }
    }
}

// ============================================================================
// Kernel B: per-node attention (frozen since R6).
// ============================================================================
__global__ void __launch_bounds__(256) attn_kernel(
    const int* __restrict__ adj,
    const int* __restrict__ deg,
    float* __restrict__ out)
{
    __shared__ float s_buf[8][KNBR];

    const unsigned FULL = 0xffffffffu;
    const int warp = threadIdx.x >> 5;
    const int lane = threadIdx.x & 31;
    const int m    = blockIdx.x * 8 + warp;   // 6250 * 8 == 50000 exactly

    const int  d     = deg[m];
    const int  a     = adj[(size_t)m * KNBR + lane];
    const bool valid = (lane < d);

    const float NEG_INF = __int_as_float(0xff800000u);

    float e32 = NEG_INF;
    if (valid) {
        const float x = g_hc1[m] + g_hc2[a];   // fp32 add, as reference
        e32 = (x >= 0.f) ? x : 0.2f * x;
    }

    float mx = e32;
    #pragma unroll
    for (int off = 16; off > 0; off >>= 1)
        mx = fmaxf(mx, __shfl_xor_sync(FULL, mx, off));

    const float p = valid ? expf(e32 - mx) : 0.f;

    // ---- pass 1: sequential fp32 sum of p ----
    s_buf[warp][lane] = p;
    __syncwarp();
    float s = 0.f;
    #pragma unroll
    for (int q = 0; q < 8; q++) {
        const float4 v = *(const float4*)&s_buf[warp][q * 4];
        s += v.x; s += v.y; s += v.z; s += v.w;
    }

    const float att = p / s;

    // ---- pass 2: sequential fp32 prefix sum with capture-at-index ----
    __syncwarp();
    s_buf[warp][lane] = att;
    __syncwarp();
    float run = 0.f, csum = 0.f, shifted = 0.f;
    const int lm3 = lane - WSIZE;
    #pragma unroll
    for (int q = 0; q < 8; q++) {
        const float4 v = *(const float4*)&s_buf[warp][q * 4];
        const int k0 = q * 4;
        run += v.x; if (k0 + 0 == lane) csum = run; if (k0 + 0 == lm3) shifted = run;
        run += v.y; if (k0 + 1 == lane) csum = run; if (k0 + 1 == lm3) shifted = run;
        run += v.z; if (k0 + 2 == lane) csum = run; if (k0 + 2 == lm3) shifted = run;
        run += v.w; if (k0 + 3 == lane) csum = run; if (k0 + 3 == lm3) shifted = run;
    }

    float win = -1.0f;
    if (lane >= WSIZE - 1 && lane < d)
        win = csum - shifted;

    // argmax, first occurrence on ties
    float bw = win;
    int   bj = lane;
    #pragma unroll
    for (int off = 16; off > 0; off >>= 1) {
        const float ow = __shfl_down_sync(FULL, bw, off);
        const int   oj = __shfl_down_sync(FULL, bj, off);
        if (ow > bw || (ow == bw && oj < bj)) { bw = ow; bj = oj; }
    }
    const int jstar = __shfl_sync(FULL, bj, 0);

    const float scale = (float)d / 3.0f;
    const float t = (lane >= jstar - (WSIZE - 1) && lane <= jstar) ? att * scale : 0.f;

    const float w0 = __shfl_sync(FULL, t, jstar - 2);
    const float w1 = __shfl_sync(FULL, t, jstar - 1);
    const float w2 = __shfl_sync(FULL, t, jstar);
    const int   a0 = __shfl_sync(FULL, a, jstar - 2);
    const int   a1 = __shfl_sync(FULL, a, jstar - 1);
    const int   a2 = __shfl_sync(FULL, a, jstar);

    const float4 v0 = ((const float4*)(g_h + (size_t)a0 * F))[lane];
    const float4 v1 = ((const float4*)(g_h + (size_t)a1 * F))[lane];
    const float4 v2 = ((const float4*)(g_h + (size_t)a2 * F))[lane];

    float4 o;
    o.x = fmaf(w2, v2.x, fmaf(w1, v1.x, w0 * v0.x));
    o.y = fmaf(w2, v2.y, fmaf(w1, v1.y, w0 * v0.y));
    o.z = fmaf(w2, v2.z, fmaf(w1, v1.z, w0 * v0.z));
    o.w = fmaf(w2, v2.w, fmaf(w1, v1.w, w0 * v0.w));

    o.x = (o.x > 0.f) ? o.x : expm1f(o.x);
    o.y = (o.y > 0.f) ? o.y : expm1f(o.y);
    o.z = (o.z > 0.f) ? o.z : expm1f(o.z);
    o.w = (o.w > 0.f) ? o.w : expm1f(o.w);

    ((float4*)out)[(size_t)m * (F / 4) + lane] = o;
}

extern "C" void kernel_launch(void* const* d_in, const int* in_sizes, int n_in,
                              void* d_out, int out_size) {
    const float* inp = (const float*)d_in[0];
    const float* W   = (const float*)d_in[1];
    const float* c1  = (const float*)d_in[2];
    const float* c2  = (const float*)d_in[3];
    const int*   adj = (const int*)d_in[4];
    const int*   deg = (const int*)d_in[5];
    float*       out = (float*)d_out;

    gemm_kernel<<<(NN + RPB - 1) / RPB, 128>>>(inp, W);     // 1563 blocks
    hc_kernel<<<(NN + 63) / 64, 256>>>(c1, c2);             // 782 blocks
    attn_kernel<<<NN / 8, 256>>>(adj, deg, out);            // 6250 blocks
}

// round 11
// speedup vs baseline: 1.2128x; 1.2128x over previous
#include <cuda_runtime.h>
#include <math.h>

#define NN 50000          // N_NODES == M_NODES
#define KNBR 32
#define F 128
#define FP 132            // padded smem row stride (floats): 528B, 16B-aligned
#define WSIZE 3
#define RPB 32            // rows per block (4 warps x 8 rows)

typedef unsigned long long ull;

// Scratch (device globals: allocation-free per harness rules)
__device__ float g_h[(size_t)NN * F];     // h = input @ W  (fp32)
__device__ float g_hc1[NN];               // fl32( fp64-accurate h . c1 )
__device__ float g_hc2[NN];               // fl32( fp64-accurate h . c2 )

// ---- packed f32x2 helpers ----
static __device__ __forceinline__ ull pack2(float lo, float hi) {
    ull r;
    asm("mov.b64 %0, {%1, %2};" : "=l"(r) : "f"(lo), "f"(hi));
    return r;
}
static __device__ __forceinline__ void unpack2(ull v, float& lo, float& hi) {
    asm("mov.b64 {%0, %1}, %2;" : "=f"(lo), "=f"(hi) : "l"(v));
}
static __device__ __forceinline__ void ffma2(ull& d, ull a, ull b) {
    asm("fma.rn.f32x2 %0, %1, %2, %0;" : "+l"(d) : "l"(a), "l"(b));
}

// ============================================================================
// Kernel A: h = input @ W  +  fused hc epilogue (shfl-free).
// ARITHMETIC CONTRACT (bitwise, frozen):
//   h[row][c]: acc.lo = sum of in[k]*W[k][c] over even k ascending,
//              acc.hi over odd k ascending, h = lo + hi.
//   hc[row]:   p_j = h[4j]*c[4j] + h[4j+1]*c[4j+1] + h[4j+2]*c[4j+2]
//              + h[4j+3]*c[4j+3] (left-to-right, fp64), then binary tree
//              p[j] += p[j+off] for off = 16,8,4,2,1 -> p[0], stored fp32.
//   (Tree == old shfl_down reduction at lane 0, emulated in ONE thread.)
// block = 128 threads (4 warps), 32 rows/block, 8 rows/warp, 4 cols/lane.
// ============================================================================
__global__ void __launch_bounds__(128) gemm_hc_kernel(
    const float* __restrict__ inp,
    const float* __restrict__ W,
    const float* __restrict__ c1,
    const float* __restrict__ c2)
{
    __shared__ float s_in[RPB][FP];   // padded: 32 x 528B = 16.9 KB

    const int tid  = threadIdx.x;
    const int lane = tid & 31;
    const int warp = tid >> 5;
    const int row0 = blockIdx.x * RPB;

    // stage 32 input rows (1024 float4 chunks; 8 per thread)
    #pragma unroll
    for (int i = 0; i < 8; i++) {
        const int idx   = tid + i * 128;
        const int row   = idx >> 5;
        const int chunk = idx & 31;
        int grow = row0 + row;
        if (grow >= NN) grow = NN - 1;         // clamp (tail block)
        *(float4*)&s_in[row][chunk * 4] =
            ((const float4*)(inp + (size_t)grow * F))[chunk];
    }
    __syncthreads();

    ull acc[8][4];
    #pragma unroll
    for (int r = 0; r < 8; r++)
        #pragma unroll
        for (int i = 0; i < 4; i++)
            acc[r][i] = 0ULL;

    const int colbase = lane * 4;
    const int rbase   = warp * 8;

    #pragma unroll 2
    for (int k = 0; k < F; k += 2) {
        const float4 wa = *(const float4*)(W + (size_t)k * F + colbase);
        const float4 wb = *(const float4*)(W + (size_t)(k + 1) * F + colbase);
        const ull wp0 = pack2(wa.x, wb.x);
        const ull wp1 = pack2(wa.y, wb.y);
        const ull wp2 = pack2(wa.z, wb.z);
        const ull wp3 = pack2(wa.w, wb.w);
        #pragma unroll
        for (int r = 0; r < 8; r++) {
            const ull ip = *(const ull*)&s_in[rbase + r][k];  // == pack2(s[k],s[k+1])
            ffma2(acc[r][0], ip, wp0);
            ffma2(acc[r][1], ip, wp1);
            ffma2(acc[r][2], ip, wp2);
            ffma2(acc[r][3], ip, wp3);
        }
    }

    // h results: write to gmem AND stash in smem (s_in reuse — each warp only
    // touches its own 8 rows, and staging data is dead now).
    #pragma unroll
    for (int r = 0; r < 8; r++) {
        float4 hv;
        float lo, hi;
        unpack2(acc[r][0], lo, hi); hv.x = lo + hi;
        unpack2(acc[r][1], lo, hi); hv.y = lo + hi;
        unpack2(acc[r][2], lo, hi); hv.z = lo + hi;
        unpack2(acc[r][3], lo, hi); hv.w = lo + hi;

        *(float4*)&s_in[rbase + r][colbase] = hv;

        const int row = row0 + rbase + r;
        if (row < NN)
            *(float4*)(g_h + (size_t)row * F + colbase) = hv;
    }
    __syncthreads();

    // hc epilogue: thread t<32 -> d1 of row t; thread 32..63 -> d2 of row t-32.
    // In-thread tree == old shfl_down tree, bitwise.
    if (tid < 64) {
        const int t = tid & 31;
        const float* cvec = (tid < 32) ? c1 : c2;

        double p[32];
        #pragma unroll
        for (int j = 0; j < 32; j++) {
            const float4 hv4 = *(const float4*)&s_in[t][4 * j];
            const float4 cc  = *(const float4*)(cvec + 4 * j);
            p[j] = (double)hv4.x * (double)cc.x + (double)hv4.y * (double)cc.y
                 + (double)hv4.z * (double)cc.z + (double)hv4.w * (double)cc.w;
        }
        #pragma unroll
        for (int off = 16; off >= 1; off >>= 1)
            #pragma unroll
            for (int j = 0; j < off; j++)
                p[j] += p[j + off];

        const int row = row0 + t;
        if (row < NN) {
            if (tid < 32) g_hc1[row] = (float)p[0];
            else          g_hc2[row] = (float)p[0];
        }
    }
}

// ============================================================================
// Kernel B: per-node attention (frozen since R6).
// ============================================================================
__global__ void __launch_bounds__(256) attn_kernel(
    const int* __restrict__ adj,
    const int* __restrict__ deg,
    float* __restrict__ out)
{
    __shared__ float s_buf[8][KNBR];

    const unsigned FULL = 0xffffffffu;
    const int warp = threadIdx.x >> 5;
    const int lane = threadIdx.x & 31;
    const int m    = blockIdx.x * 8 + warp;   // 6250 * 8 == 50000 exactly

    const int  d     = deg[m];
    const int  a     = adj[(size_t)m * KNBR + lane];
    const bool valid = (lane < d);

    const float NEG_INF = __int_as_float(0xff800000u);

    float e32 = NEG_INF;
    if (valid) {
        const float x = g_hc1[m] + g_hc2[a];   // fp32 add, as reference
        e32 = (x >= 0.f) ? x : 0.2f * x;
    }

    float mx = e32;
    #pragma unroll
    for (int off = 16; off > 0; off >>= 1)
        mx = fmaxf(mx, __shfl_xor_sync(FULL, mx, off));

    const float p = valid ? expf(e32 - mx) : 0.f;

    // ---- pass 1: sequential fp32 sum of p ----
    s_buf[warp][lane] = p;
    __syncwarp();
    float s = 0.f;
    #pragma unroll
    for (int q = 0; q < 8; q++) {
        const float4 v = *(const float4*)&s_buf[warp][q * 4];
        s += v.x; s += v.y; s += v.z; s += v.w;
    }

    const float att = p / s;

    // ---- pass 2: sequential fp32 prefix sum with capture-at-index ----
    __syncwarp();
    s_buf[warp][lane] = att;
    __syncwarp();
    float run = 0.f, csum = 0.f, shifted = 0.f;
    const int lm3 = lane - WSIZE;
    #pragma unroll
    for (int q = 0; q < 8; q++) {
        const float4 v = *(const float4*)&s_buf[warp][q * 4];
        const int k0 = q * 4;
        run += v.x; if (k0 + 0 == lane) csum = run; if (k0 + 0 == lm3) shifted = run;
        run += v.y; if (k0 + 1 == lane) csum = run; if (k0 + 1 == lm3) shifted = run;
        run += v.z; if (k0 + 2 == lane) csum = run; if (k0 + 2 == lm3) shifted = run;
        run += v.w; if (k0 + 3 == lane) csum = run; if (k0 + 3 == lm3) shifted = run;
    }

    float win = -1.0f;
    if (lane >= WSIZE - 1 && lane < d)
        win = csum - shifted;

    // argmax, first occurrence on ties
    float bw = win;
    int   bj = lane;
    #pragma unroll
    for (int off = 16; off > 0; off >>= 1) {
        const float ow = __shfl_down_sync(FULL, bw, off);
        const int   oj = __shfl_down_sync(FULL, bj, off);
        if (ow > bw || (ow == bw && oj < bj)) { bw = ow; bj = oj; }
    }
    const int jstar = __shfl_sync(FULL, bj, 0);

    const float scale = (float)d / 3.0f;
    const float t = (lane >= jstar - (WSIZE - 1) && lane <= jstar) ? att * scale : 0.f;

    const float w0 = __shfl_sync(FULL, t, jstar - 2);
    const float w1 = __shfl_sync(FULL, t, jstar - 1);
    const float w2 = __shfl_sync(FULL, t, jstar);
    const int   a0 = __shfl_sync(FULL, a, jstar - 2);
    const int   a1 = __shfl_sync(FULL, a, jstar - 1);
    const int   a2 = __shfl_sync(FULL, a, jstar);

    const float4 v0 = ((const float4*)(g_h + (size_t)a0 * F))[lane];
    const float4 v1 = ((const float4*)(g_h + (size_t)a1 * F))[lane];
    const float4 v2 = ((const float4*)(g_h + (size_t)a2 * F))[lane];

    float4 o;
    o.x = fmaf(w2, v2.x, fmaf(w1, v1.x, w0 * v0.x));
    o.y = fmaf(w2, v2.y, fmaf(w1, v1.y, w0 * v0.y));
    o.z = fmaf(w2, v2.z, fmaf(w1, v1.z, w0 * v0.z));
    o.w = fmaf(w2, v2.w, fmaf(w1, v1.w, w0 * v0.w));

    o.x = (o.x > 0.f) ? o.x : expm1f(o.x);
    o.y = (o.y > 0.f) ? o.y : expm1f(o.y);
    o.z = (o.z > 0.f) ? o.z : expm1f(o.z);
    o.w = (o.w > 0.f) ? o.w : expm1f(o.w);

    ((float4*)out)[(size_t)m * (F / 4) + lane] = o;
}

extern "C" void kernel_launch(void* const* d_in, const int* in_sizes, int n_in,
                              void* d_out, int out_size) {
    const float* inp = (const float*)d_in[0];
    const float* W   = (const float*)d_in[1];
    const float* c1  = (const float*)d_in[2];
    const float* c2  = (const float*)d_in[3];
    const int*   adj = (const int*)d_in[4];
    const int*   deg = (const int*)d_in[5];
    float*       out = (float*)d_out;

    gemm_hc_kernel<<<(NN + RPB - 1) / RPB, 128>>>(inp, W, c1, c2);  // 1563 blocks
    attn_kernel<<<NN / 8, 256>>>(adj, deg, out);                    // 6250 blocks
}